// round 1
// baseline (speedup 1.0000x reference)
#include <cuda_runtime.h>
#include <math.h>

typedef unsigned long long u64;

// Packed fp32x2 FMA (Blackwell FFMA2) — lanes carry even/odd-k partial sums.
#define FMA2(d, a, b, c) \
    asm("fma.rn.f32x2 %0, %1, %2, %3;" : "=l"(d) : "l"(a), "l"(b), "l"(c))

__device__ __forceinline__ u64 pack2(float lo, float hi) {
    u64 r;
    asm("mov.b64 %0, {%1,%2};" : "=l"(r) : "f"(lo), "f"(hi));
    return r;
}
__device__ __forceinline__ float unpack_sum(u64 v) {
    float x, y;
    asm("mov.b64 {%0,%1}, %2;" : "=f"(x), "=f"(y) : "l"(v));
    return x + y;
}

// fast-math-proof tanh: accurate fp32 via __expf, no dependence on tanhf lowering
__device__ __forceinline__ float my_tanh(float x) {
    float ax = fabsf(x);
    float e  = __expf(2.0f * ax);          // inf for large ax -> r = 1
    float r  = 1.0f - 2.0f / (e + 1.0f);
    return copysignf(r, x);
}

constexpr int BATCH = 4096;
constexpr int KIN   = 64;    // k_in == k_out == 64
constexpr int KS    = 256;   // k_state
constexpr int TPRE  = 64;
constexpr int TFWD  = 80;
constexpr int BC    = 32;    // batch rows per CTA
constexpr int NT    = 256;   // threads per CTA

// Fully fused persistent kernel: encoder RNN + SSM rollout + output projection.
// Each CTA owns BC batch rows end-to-end; no inter-CTA communication.
__global__ __launch_bounds__(NT, 1) void ss_fused(
    const float* __restrict__ pre_x,   // [64,4096,64]
    const float* __restrict__ pre_y,   // [64,4096,64]
    const float* __restrict__ fwd_x,   // [80,4096,64]
    const float* __restrict__ A_w,     // [256,256]
    const float* __restrict__ A_b,     // [256]
    const float* __restrict__ B_w,     // [256,64]
    const float* __restrict__ B_b,     // [256]
    const float* __restrict__ C_w,     // [64,256]
    const float* __restrict__ C_b,     // [64]
    const float* __restrict__ W_ih,    // [256,128]
    const float* __restrict__ b_ih,    // [256]
    const float* __restrict__ W_hh,    // [256,256]
    const float* __restrict__ b_hh,    // [256]
    float* __restrict__ out)           // [80,4096,64]
{
    __shared__ float hs[BC][KS];        // 32 KB hidden state
    __shared__ float xs[BC][2 * KIN];   // 16 KB staged inputs

    const int tid    = threadIdx.x;
    const int lane64 = tid & 63;        // j-lane (also o-lane for output proj)
    const int b0g    = (tid >> 6) * 8;  // this thread's batch sub-block base
    const int bbase  = blockIdx.x * BC;

    // zero hidden state
    for (int i = tid; i < BC * KS; i += NT) (&hs[0][0])[i] = 0.0f;

    // fold biases once
    float enc_bias[4], ssm_bias[4];
#pragma unroll
    for (int jj = 0; jj < 4; jj++) {
        int j = lane64 + 64 * jj;
        enc_bias[jj] = b_ih[j] + b_hh[j];
        ssm_bias[jj] = A_b[j] + B_b[j];
    }
    const float cbias = C_b[lane64];

    // weight rows viewed as packed k-pairs
    const u64* Wih2 = (const u64*)W_ih;  // row stride 64  u64
    const u64* Whh2 = (const u64*)W_hh;  // row stride 128 u64
    const u64* Aw2  = (const u64*)A_w;   // row stride 128 u64
    const u64* Bw2  = (const u64*)B_w;   // row stride 32  u64
    const u64* Cw2  = (const u64*)C_w;   // row stride 128 u64

    // ---------------- encoder: h = tanh(W_ih*xy + W_hh*h + biases) ----------------
    for (int t = 0; t < TPRE; t++) {
        __syncthreads();   // prev-step h visible; xs free for reuse
        {
            const float* px = pre_x + ((size_t)t * BATCH + bbase) * KIN;
            const float* py = pre_y + ((size_t)t * BATCH + bbase) * KIN;
            for (int i = tid; i < BC * KIN; i += NT) {
                int b = i >> 6, k = i & 63;
                xs[b][k]       = px[b * KIN + k];
                xs[b][KIN + k] = py[b * KIN + k];
            }
        }
        __syncthreads();

        u64 acc[4][8];
#pragma unroll
        for (int jj = 0; jj < 4; jj++)
#pragma unroll
            for (int bb = 0; bb < 8; bb++) acc[jj][bb] = pack2(enc_bias[jj], 0.0f);

        // input projection part: K = 128 (64 k-pairs)
#pragma unroll 4
        for (int k2 = 0; k2 < 64; k2++) {
            u64 w[4], hh[8];
#pragma unroll
            for (int jj = 0; jj < 4; jj++)
                w[jj] = __ldg(&Wih2[(lane64 + 64 * jj) * 64 + k2]);
#pragma unroll
            for (int bb = 0; bb < 8; bb++)
                hh[bb] = ((const u64*)&xs[b0g + bb][0])[k2];
#pragma unroll
            for (int jj = 0; jj < 4; jj++)
#pragma unroll
                for (int bb = 0; bb < 8; bb++)
                    FMA2(acc[jj][bb], w[jj], hh[bb], acc[jj][bb]);
        }
        // recurrent part: K = 256 (128 k-pairs)
#pragma unroll 4
        for (int k2 = 0; k2 < 128; k2++) {
            u64 w[4], hh[8];
#pragma unroll
            for (int jj = 0; jj < 4; jj++)
                w[jj] = __ldg(&Whh2[(lane64 + 64 * jj) * 128 + k2]);
#pragma unroll
            for (int bb = 0; bb < 8; bb++)
                hh[bb] = ((const u64*)&hs[b0g + bb][0])[k2];
#pragma unroll
            for (int jj = 0; jj < 4; jj++)
#pragma unroll
                for (int bb = 0; bb < 8; bb++)
                    FMA2(acc[jj][bb], w[jj], hh[bb], acc[jj][bb]);
        }
        __syncthreads();   // all reads of old h done
#pragma unroll
        for (int jj = 0; jj < 4; jj++)
#pragma unroll
            for (int bb = 0; bb < 8; bb++)
                hs[b0g + bb][lane64 + 64 * jj] = my_tanh(unpack_sum(acc[jj][bb]));
    }

    // ---------------- SSM rollout: h = A*h + B*x + biases; y = C*h + C_b ----------------
    for (int t = 0; t < TFWD; t++) {
        __syncthreads();   // h written; previous y reads done; xs free
        {
            const float* fx = fwd_x + ((size_t)t * BATCH + bbase) * KIN;
            for (int i = tid; i < BC * KIN; i += NT) {
                int b = i >> 6, k = i & 63;
                xs[b][k] = fx[b * KIN + k];
            }
        }
        __syncthreads();

        u64 acc[4][8];
#pragma unroll
        for (int jj = 0; jj < 4; jj++)
#pragma unroll
            for (int bb = 0; bb < 8; bb++) acc[jj][bb] = pack2(ssm_bias[jj], 0.0f);

        // B*x part: K = 64 (32 k-pairs)
#pragma unroll 4
        for (int k2 = 0; k2 < 32; k2++) {
            u64 w[4], hh[8];
#pragma unroll
            for (int jj = 0; jj < 4; jj++)
                w[jj] = __ldg(&Bw2[(lane64 + 64 * jj) * 32 + k2]);
#pragma unroll
            for (int bb = 0; bb < 8; bb++)
                hh[bb] = ((const u64*)&xs[b0g + bb][0])[k2];
#pragma unroll
            for (int jj = 0; jj < 4; jj++)
#pragma unroll
                for (int bb = 0; bb < 8; bb++)
                    FMA2(acc[jj][bb], w[jj], hh[bb], acc[jj][bb]);
        }
        // A*h part: K = 256 (128 k-pairs)
#pragma unroll 4
        for (int k2 = 0; k2 < 128; k2++) {
            u64 w[4], hh[8];
#pragma unroll
            for (int jj = 0; jj < 4; jj++)
                w[jj] = __ldg(&Aw2[(lane64 + 64 * jj) * 128 + k2]);
#pragma unroll
            for (int bb = 0; bb < 8; bb++)
                hh[bb] = ((const u64*)&hs[b0g + bb][0])[k2];
#pragma unroll
            for (int jj = 0; jj < 4; jj++)
#pragma unroll
                for (int bb = 0; bb < 8; bb++)
                    FMA2(acc[jj][bb], w[jj], hh[bb], acc[jj][bb]);
        }
        __syncthreads();   // old-h reads done
#pragma unroll
        for (int jj = 0; jj < 4; jj++)
#pragma unroll
            for (int bb = 0; bb < 8; bb++)
                hs[b0g + bb][lane64 + 64 * jj] = unpack_sum(acc[jj][bb]);
        __syncthreads();   // new h visible for output projection

        // y = C*h + C_b : o = lane64 (64 outputs), 8 batch rows per thread
        u64 ya[8];
#pragma unroll
        for (int bb = 0; bb < 8; bb++) ya[bb] = pack2(cbias, 0.0f);
#pragma unroll 4
        for (int k2 = 0; k2 < 128; k2++) {
            u64 c = __ldg(&Cw2[lane64 * 128 + k2]);
#pragma unroll
            for (int bb = 0; bb < 8; bb++) {
                u64 hh = ((const u64*)&hs[b0g + bb][0])[k2];
                FMA2(ya[bb], c, hh, ya[bb]);
            }
        }
        float* op = out + ((size_t)t * BATCH + bbase) * 64;
#pragma unroll
        for (int bb = 0; bb < 8; bb++)
            op[(b0g + bb) * 64 + lane64] = unpack_sum(ya[bb]);
    }
}

extern "C" void kernel_launch(void* const* d_in, const int* in_sizes, int n_in,
                              void* d_out, int out_size) {
    const float* pre_x = (const float*)d_in[0];
    const float* pre_y = (const float*)d_in[1];
    const float* fwd_x = (const float*)d_in[2];
    const float* A_w   = (const float*)d_in[3];
    const float* A_b   = (const float*)d_in[4];
    const float* B_w   = (const float*)d_in[5];
    const float* B_b   = (const float*)d_in[6];
    const float* C_w   = (const float*)d_in[7];
    const float* C_b   = (const float*)d_in[8];
    const float* W_ih  = (const float*)d_in[9];
    const float* b_ih  = (const float*)d_in[10];
    const float* W_hh  = (const float*)d_in[11];
    const float* b_hh  = (const float*)d_in[12];
    float* out = (float*)d_out;

    ss_fused<<<BATCH / BC, NT>>>(pre_x, pre_y, fwd_x, A_w, A_b, B_w, B_b,
                                 C_w, C_b, W_ih, b_ih, W_hh, b_hh, out);
}

// round 4
// speedup vs baseline: 2.9865x; 2.9865x over previous
#include <cuda_runtime.h>
#include <math.h>

typedef unsigned long long u64;
typedef unsigned int u32;

#define FMA2(d, a, b, c) \
    asm("fma.rn.f32x2 %0, %1, %2, %3;" : "=l"(d) : "l"(a), "l"(b), "l"(c))

__device__ __forceinline__ u64 pack2(float lo, float hi) {
    u64 r;
    asm("mov.b64 %0, {%1,%2};" : "=l"(r) : "f"(lo), "f"(hi));
    return r;
}
__device__ __forceinline__ float unpack_sum(u64 v) {
    float x, y;
    asm("mov.b64 {%0,%1}, %2;" : "=f"(x), "=f"(y) : "l"(v));
    return x + y;
}
__device__ __forceinline__ float my_tanh(float x) {
    float ax = fabsf(x);
    float e  = __expf(2.0f * ax);
    float r  = 1.0f - 2.0f / (e + 1.0f);
    return copysignf(r, x);
}

__device__ __forceinline__ u32 smem_u32(const void* p) {
    u32 a;
    asm("{ .reg .u64 t; cvta.to.shared.u64 t, %1; cvt.u32.u64 %0, t; }" : "=r"(a) : "l"(p));
    return a;
}

#define LDS128(v0, v1, addr) \
    asm volatile("ld.shared.v2.u64 {%0,%1}, [%2];" : "=l"(v0), "=l"(v1) : "r"(addr))
#define LDS64(v, addr) \
    asm volatile("ld.shared.u64 %0, [%1];" : "=l"(v) : "r"(addr))
#define STS64(addr, v) \
    asm volatile("st.shared.u64 [%0], %1;" :: "r"(addr), "l"(v))
#define STS32(addr, f) \
    asm volatile("st.shared.f32 [%0], %1;" :: "r"(addr), "f"(f))
#define LDS32(f, addr) \
    asm volatile("ld.shared.f32 %0, [%1];" : "=f"(f) : "r"(addr))

__device__ __forceinline__ void bulk_cp(u32 dst, const void* src, u32 bytes, u32 mbar) {
    asm volatile("cp.async.bulk.shared::cta.global.mbarrier::complete_tx::bytes [%0], [%1], %2, [%3];"
                 :: "r"(dst), "l"(src), "r"(bytes), "r"(mbar) : "memory");
}
__device__ __forceinline__ void expect_tx(u32 mbar, u32 bytes) {
    asm volatile("mbarrier.arrive.expect_tx.shared::cta.b64 _, [%0], %1;"
                 :: "r"(mbar), "r"(bytes) : "memory");
}
__device__ __forceinline__ void mbar_wait(u32 mbar, u32 parity) {
    asm volatile("{\n\t.reg .pred p;\nLW%=:\n\t"
                 "mbarrier.try_wait.parity.shared::cta.b64 p, [%0], %1;\n\t"
                 "@!p bra LW%=;\n\t}" :: "r"(mbar), "r"(parity) : "memory");
}

constexpr int BATCH = 4096;
constexpr int BC    = 32;      // batch rows per CTA (= lane)
constexpr int NT    = 256;     // 8 warps
constexpr int TPRE  = 64;
constexpr int TFWD  = 80;

// ---- smem layout (byte offsets) ----
constexpr u32 WBUF_SZ  = 49152;                 // per buffer: up to ih(16K)+hh(32K)
constexpr u32 OFF_WBUF = 0;                     // 2 buffers
constexpr u32 HS_SZ    = 128 * 33 * 8;          // 33792 ; hs[kpair][b] u64, pitch 33
constexpr u32 OFF_HS   = 2 * WBUF_SZ;           // 98304 ; double-buffered h
constexpr u32 OFF_XS   = OFF_HS + 2 * HS_SZ;    // 165888; xs[kpair][b], 64 rows
constexpr u32 OFF_YS   = OFF_XS + 64 * 33 * 8;  // 182784; ys[32][65] f32
constexpr u32 OFF_ENCB = OFF_YS + 32 * 65 * 4;  // 191104
constexpr u32 OFF_SSMB = OFF_ENCB + 1024;       // 192128
constexpr u32 OFF_CB   = OFF_SSMB + 1024;       // 193152
constexpr u32 OFF_MBAR = 193408;
constexpr u32 SMEM_TOTAL = 193536;

// Compute a 4-row j-tile over KCTOT k-chunks (32 kpairs each). First KCX chunks
// read xs (weight pitch wxp), the rest read h (pitch whp). Weights are smem
// broadcasts (LDS.128); h/x chunks are lane-consecutive LDS.64 cached in regs.
template <int KCX, int KCTOT>
__device__ __forceinline__ void chunk_mma(
    u32 wxa, int wxp, u32 wha, int whp,
    u32 xsa, u32 hsa, int lane8, u64 acc[4])
{
#pragma unroll 1
    for (int kc = 0; kc < KCTOT; kc++) {
        const bool isx = (KCX > 0) && (kc < KCX);
        u32 hb = (isx ? xsa + kc * 32 * 33 * 8
                      : hsa + (kc - KCX) * 32 * 33 * 8) + lane8;
        u64 hk[32];
#pragma unroll
        for (int i = 0; i < 32; i++) LDS64(hk[i], hb + i * 33 * 8);

        u32 wb = isx ? (wxa + kc * 256) : (wha + (kc - KCX) * 256);
        int wp = isx ? wxp : whp;
#pragma unroll
        for (int jj = 0; jj < 4; jj++) {
            u32 wr = wb + jj * wp;
#pragma unroll
            for (int kp = 0; kp < 32; kp += 2) {
                u64 w0, w1;
                LDS128(w0, w1, wr + kp * 8);
                FMA2(acc[jj], w0, hk[kp], acc[jj]);
                FMA2(acc[jj], w1, hk[kp + 1], acc[jj]);
            }
        }
    }
}

__global__ __launch_bounds__(NT, 1) void ss_fused(
    const float* __restrict__ pre_x, const float* __restrict__ pre_y,
    const float* __restrict__ fwd_x,
    const float* __restrict__ A_w, const float* __restrict__ A_b,
    const float* __restrict__ B_w, const float* __restrict__ B_b,
    const float* __restrict__ C_w, const float* __restrict__ C_b,
    const float* __restrict__ W_ih, const float* __restrict__ b_ih,
    const float* __restrict__ W_hh, const float* __restrict__ b_hh,
    float* __restrict__ out)
{
    extern __shared__ char smem[];
    const u32 SB = smem_u32(smem);
    const int tid = threadIdx.x, lane = tid & 31, warp = tid >> 5;
    const int lane8 = lane * 8;
    const int bbase = blockIdx.x * BC;

    // folded biases into smem
    {
        STS32(SB + OFF_ENCB + tid * 4, b_ih[tid] + b_hh[tid]);
        STS32(SB + OFF_SSMB + tid * 4, A_b[tid] + B_b[tid]);
        if (tid < 64) STS32(SB + OFF_CB + tid * 4, C_b[tid]);
    }
    // zero h buffer 0
    for (int i = tid; i < 128 * 33; i += NT) STS64(SB + OFF_HS + i * 8, 0ULL);
    if (tid == 0) {
        asm volatile("mbarrier.init.shared::cta.b64 [%0], 1;" :: "r"(SB + OFF_MBAR) : "memory");
        asm volatile("mbarrier.init.shared::cta.b64 [%0], 1;" :: "r"(SB + OFF_MBAR + 8) : "memory");
        asm volatile("fence.proxy.async.shared::cta;" ::: "memory");
    }
    __syncthreads();

    int cur = 0;
    u32 ph0 = 0, ph1 = 0;
#define BAR(b)  (SB + OFF_MBAR + (u32)(b) * 8)
#define WBA(b)  (SB + OFF_WBUF + (u32)(b) * WBUF_SZ)
#define WAIT_FLIP(b) do { if (b) { mbar_wait(BAR(1), ph1); ph1 ^= 1; } \
                          else   { mbar_wait(BAR(0), ph0); ph0 ^= 1; } } while (0)

    // ================= encoder =================
    for (int t = 0; t < TPRE; t++) {
        if (tid == 0) {
            expect_tx(BAR(0), 49152);
            bulk_cp(WBA(0), W_ih, 16384, BAR(0));
            bulk_cp(WBA(0) + 16384, W_hh, 32768, BAR(0));
        }
        // stage xy transposed: xs[kpair][b] (pairs 0..31 = x, 32..63 = y)
        const float* px = pre_x + ((size_t)t * BATCH + bbase) * 64;
        const float* py = pre_y + ((size_t)t * BATCH + bbase) * 64;
        for (int i = tid; i < 2048; i += NT) {
            int b = i >> 6, k = i & 63;
            STS32(SB + OFF_XS + ((u32)((k >> 1) * 33 + b) * 8) + (u32)(k & 1) * 4,
                  __ldg(&px[b * 64 + k]));
            STS32(SB + OFF_XS + ((u32)((32 + (k >> 1)) * 33 + b) * 8) + (u32)(k & 1) * 4,
                  __ldg(&py[b * 64 + k]));
        }
        __syncthreads();   // xs staged for all

        const u32 hcur = SB + OFF_HS + (u32)cur * HS_SZ;
        const u32 hnxt = SB + OFF_HS + (u32)(cur ^ 1) * HS_SZ;

        for (int c = 0; c < 8; c++) {
            const int cb = c & 1, nb = cb ^ 1;
            if (c < 7 && tid == 0) {
                expect_tx(BAR(nb), 49152);
                bulk_cp(WBA(nb), (const char*)W_ih + (c + 1) * 16384, 16384, BAR(nb));
                bulk_cp(WBA(nb) + 16384, (const char*)W_hh + (c + 1) * 32768, 32768, BAR(nb));
            }
            WAIT_FLIP(cb);

            u64 acc[4] = {0ULL, 0ULL, 0ULL, 0ULL};
            chunk_mma<2, 6>(WBA(cb) + (u32)(warp * 4) * 512, 512,
                            WBA(cb) + 16384 + (u32)(warp * 4) * 1024, 1024,
                            SB + OFF_XS, hcur, lane8, acc);

            const int j0 = c * 32 + warp * 4;
            float nh[4];
#pragma unroll
            for (int jj = 0; jj < 4; jj++) {
                float bs; LDS32(bs, SB + OFF_ENCB + (u32)(j0 + jj) * 4);
                nh[jj] = my_tanh(unpack_sum(acc[jj]) + bs);
            }
            const u32 r = hnxt + (u32)((j0 >> 1) * 33) * 8 + lane8;
            STS64(r, pack2(nh[0], nh[1]));
            STS64(r + 33 * 8, pack2(nh[2], nh[3]));
            __syncthreads();
        }
        cur ^= 1;
    }

    // ================= SSM rollout + output =================
    for (int t = 0; t < TFWD; t++) {
        if (tid == 0) {
            expect_tx(BAR(0), 40960);
            bulk_cp(WBA(0), B_w, 8192, BAR(0));
            bulk_cp(WBA(0) + 8192, A_w, 32768, BAR(0));
        }
        const float* fx = fwd_x + ((size_t)t * BATCH + bbase) * 64;
        for (int i = tid; i < 2048; i += NT) {
            int b = i >> 6, k = i & 63;
            STS32(SB + OFF_XS + ((u32)((k >> 1) * 33 + b) * 8) + (u32)(k & 1) * 4,
                  __ldg(&fx[b * 64 + k]));
        }
        __syncthreads();

        const u32 hcur = SB + OFF_HS + (u32)cur * HS_SZ;
        const u32 hnxt = SB + OFF_HS + (u32)(cur ^ 1) * HS_SZ;

        for (int c = 0; c < 8; c++) {
            const int cb = c & 1, nb = cb ^ 1;
            if (tid == 0) {
                if (c < 7) {
                    expect_tx(BAR(nb), 40960);
                    bulk_cp(WBA(nb), (const char*)B_w + (c + 1) * 8192, 8192, BAR(nb));
                    bulk_cp(WBA(nb) + 8192, (const char*)A_w + (c + 1) * 32768, 32768, BAR(nb));
                } else {
                    expect_tx(BAR(nb), 32768);     // C chunk 0
                    bulk_cp(WBA(nb), C_w, 32768, BAR(nb));
                }
            }
            WAIT_FLIP(cb);

            u64 acc[4] = {0ULL, 0ULL, 0ULL, 0ULL};
            chunk_mma<1, 5>(WBA(cb) + (u32)(warp * 4) * 256, 256,
                            WBA(cb) + 8192 + (u32)(warp * 4) * 1024, 1024,
                            SB + OFF_XS, hcur, lane8, acc);

            const int j0 = c * 32 + warp * 4;
            float nh[4];
#pragma unroll
            for (int jj = 0; jj < 4; jj++) {
                float bs; LDS32(bs, SB + OFF_SSMB + (u32)(j0 + jj) * 4);
                nh[jj] = unpack_sum(acc[jj]) + bs;
            }
            const u32 r = hnxt + (u32)((j0 >> 1) * 33) * 8 + lane8;
            STS64(r, pack2(nh[0], nh[1]));
            STS64(r + 33 * 8, pack2(nh[2], nh[3]));
            __syncthreads();
        }

        // output projection: y = C * h_new + C_b  (2 chunks of 32 o-rows)
        for (int cc = 0; cc < 2; cc++) {
            const int c = 8 + cc, cb = c & 1, nb = cb ^ 1;
            if (cc == 0 && tid == 0) {
                expect_tx(BAR(nb), 32768);         // C chunk 1
                bulk_cp(WBA(nb), (const char*)C_w + 32768, 32768, BAR(nb));
            }
            WAIT_FLIP(cb);

            u64 acc[4] = {0ULL, 0ULL, 0ULL, 0ULL};
            chunk_mma<0, 4>(0, 0, WBA(cb) + (u32)(warp * 4) * 1024, 1024,
                            0, hnxt, lane8, acc);

            const int o0 = cc * 32 + warp * 4;
#pragma unroll
            for (int jj = 0; jj < 4; jj++) {
                float bs; LDS32(bs, SB + OFF_CB + (u32)(o0 + jj) * 4);
                STS32(SB + OFF_YS + (u32)(lane * 65 + o0 + jj) * 4,
                      unpack_sum(acc[jj]) + bs);
            }
            __syncthreads();
        }

        // stream y tile to gmem, coalesced
        float* op = out + ((size_t)t * BATCH + bbase) * 64;
        for (int i = tid; i < 2048; i += NT) {
            int b = i >> 6, o = i & 63;
            float v; LDS32(v, SB + OFF_YS + (u32)(b * 65 + o) * 4);
            op[b * 64 + o] = v;
        }
        cur ^= 1;
    }
#undef BAR
#undef WBA
#undef WAIT_FLIP
}

extern "C" void kernel_launch(void* const* d_in, const int* in_sizes, int n_in,
                              void* d_out, int out_size) {
    const float* pre_x = (const float*)d_in[0];
    const float* pre_y = (const float*)d_in[1];
    const float* fwd_x = (const float*)d_in[2];
    const float* A_w   = (const float*)d_in[3];
    const float* A_b   = (const float*)d_in[4];
    const float* B_w   = (const float*)d_in[5];
    const float* B_b   = (const float*)d_in[6];
    const float* C_w   = (const float*)d_in[7];
    const float* C_b   = (const float*)d_in[8];
    const float* W_ih  = (const float*)d_in[9];
    const float* b_ih  = (const float*)d_in[10];
    const float* W_hh  = (const float*)d_in[11];
    const float* b_hh  = (const float*)d_in[12];
    float* out = (float*)d_out;

    cudaFuncSetAttribute(ss_fused, cudaFuncAttributeMaxDynamicSharedMemorySize,
                         SMEM_TOTAL);
    ss_fused<<<BATCH / BC, NT, SMEM_TOTAL>>>(pre_x, pre_y, fwd_x, A_w, A_b,
                                             B_w, B_b, C_w, C_b, W_ih, b_ih,
                                             W_hh, b_hh, out);
}